// round 11
// baseline (speedup 1.0000x reference)
#include <cuda_runtime.h>
#include <cuda_bf16.h>
#include <cstdint>

// ---------------------------------------------------------------------------
// Shapes:  X:(16,4096,512)  W1:(512,256) b1:(256)  W2:(256,64) b2:(64)
//          Wq/Wk/Wv/Wa:(64,64) ba:(64)  Wd:(64,512) bd:(512)
// PATCH=16 STRIDE=8 TOPK=8 EPS=1e-8 ; h=511 ; N=B*h=8176 ; M=B*L=65536
// ---------------------------------------------------------------------------
#define MROWS 65536
#define DDIM  512
#define H1DIM 256
#define EDIM  64
#define NPAT  511
#define NROWS 8176

__device__ float g_H1[(size_t)MROWS * H1DIM];   // 64 MB
__device__ float g_Xe[(size_t)MROWS * EDIM];    // 16 MB
__device__ float g_P [(size_t)NROWS * EDIM];    //  2 MB
__device__ float g_Z [(size_t)NROWS * EDIM];    //  2 MB
// W1 split into bf16 hi/lo, transposed to [N=256][K=512] (K-major rows)
__device__ __nv_bfloat16 g_W1h[256 * 512];
__device__ __nv_bfloat16 g_W1l[256 * 512];

// ---------------------------------------------------------------------------
__device__ __forceinline__ uint32_t smem_u32(const void* p) {
    uint32_t a;
    asm("{ .reg .u64 t; cvta.to.shared.u64 t, %1; cvt.u32.u64 %0, t; }"
        : "=r"(a) : "l"(p));
    return a;
}
__device__ __forceinline__ uint32_t sw128(uint32_t off) {
    return off ^ ((off >> 3) & 0x70);
}
__device__ __forceinline__ uint32_t packbf(float a, float b) {
    __nv_bfloat162 t = __floats2bfloat162_rn(a, b);
    return *(uint32_t*)&t;
}

#define LDSM4(r, addr) \
    asm volatile("ldmatrix.sync.aligned.m8n8.x4.shared.b16 {%0,%1,%2,%3}, [%4];" \
        : "=r"((r)[0]), "=r"((r)[1]), "=r"((r)[2]), "=r"((r)[3]) : "r"(addr))

#define MMA_BF16(c, a, b0, b1) \
    asm volatile("mma.sync.aligned.m16n8k16.row.col.f32.bf16.bf16.f32 " \
        "{%0,%1,%2,%3}, {%4,%5,%6,%7}, {%8,%9}, {%0,%1,%2,%3};" \
        : "+f"((c)[0]), "+f"((c)[1]), "+f"((c)[2]), "+f"((c)[3]) \
        : "r"((a)[0]), "r"((a)[1]), "r"((a)[2]), "r"((a)[3]), "r"(b0), "r"(b1))

// ---------------------------------------------------------------------------
// K0: prep W1 -> bf16 hi/lo split, transposed to [N][K]
// ---------------------------------------------------------------------------
__global__ void k_prepW1(const float* __restrict__ W1)
{
    int idx = blockIdx.x * 256 + threadIdx.x;      // over 512*256
    int k = idx >> 8;
    int n = idx & 255;
    float w = W1[idx];
    __nv_bfloat16 hi = __float2bfloat16(w);
    float rem = w - __bfloat162float(hi);
    g_W1h[n * 512 + k] = hi;
    g_W1l[n * 512 + k] = __float2bfloat16(rem);
}

// ---------------------------------------------------------------------------
// K1: H1 = leaky(X @ W1 + b1) via mma.sync bf16 split (AhBh + AhBl + AlBh).
// Block tile 128(M) x 128(N), 8 warps (4Mx2N), warp tile 32x64, K chunks of 64.
// smem: ctrl 1K | A_hi 16K | A_lo 16K | B_hi 16K | B_lo 16K = 65.5 KB dynamic.
// ---------------------------------------------------------------------------
#define E1_AH 1024
#define E1_AL (1024 + 16384)
#define E1_BH (1024 + 32768)
#define E1_BL (1024 + 49152)
#define E1_SMEM (1024 + 65536)

__global__ __launch_bounds__(256)
void k_enc1_mma(const float* __restrict__ X, const float* __restrict__ bias1)
{
    extern __shared__ char smem[];
    const uint32_t sb = smem_u32(smem);
    const int tid  = threadIdx.x;
    const int lane = tid & 31;
    const int wid  = tid >> 5;
    const int wm   = (wid & 3) * 32;     // warp m-offset in tile
    const int wn   = (wid >> 2) * 64;    // warp n-offset in tile
    const int bm   = blockIdx.x * 128;
    const int bn   = blockIdx.y * 128;
    const float* Arow = X + (size_t)bm * DDIM;

    // ldmatrix per-thread addressing.
    // A x4 quadrant order (0,0),(8,0),(0,8),(8,8):
    const int a_r  = wm + ((lane >> 3) & 1) * 8 + (lane & 7);
    const int a_kb = ((lane >> 4) & 1) * 16;
    // B x4 tile order (n0,k0),(n0,k16B),(n8,k0),(n8,k16B):
    const int b_n  = wn + ((lane >> 4) & 1) * 8 + (lane & 7);
    const int b_kb = ((lane >> 3) & 1) * 16;

    float acc[2][8][4] = {};

    #pragma unroll 1
    for (int s = 0; s < 8; ++s) {
        // prefetch A f32 tile (128 x 64) and B bf16 tiles into registers
        float4 av[8];
        #pragma unroll
        for (int u = 0; u < 8; ++u) {
            int f = tid + u * 256;               // flat float4 id
            int r = f >> 4, k4 = f & 15;
            av[u] = *(const float4*)(Arow + (size_t)r * DDIM + s * 64 + k4 * 4);
        }
        float4 bh[4], bl[4];
        #pragma unroll
        for (int u = 0; u < 4; ++u) {
            int f = tid + u * 256;               // flat 16B id, 0..1023
            int n = f >> 3, kq = f & 7;
            size_t src = (size_t)(bn + n) * 512 + (size_t)s * 64 + (size_t)kq * 8;
            bh[u] = *(const float4*)(g_W1h + src);
            bl[u] = *(const float4*)(g_W1l + src);
        }

        __syncthreads();    // previous chunk's compute done before overwrite

        // A: convert f32 -> bf16 hi/lo into SW128 smem (128B rows)
        #pragma unroll
        for (int u = 0; u < 8; ++u) {
            int f = tid + u * 256;
            int r = f >> 4, k4 = f & 15;
            uint32_t off = (uint32_t)(r * 128 + k4 * 8);
            float x = av[u].x, y = av[u].y, z = av[u].z, w = av[u].w;
            __nv_bfloat16 hx = __float2bfloat16(x), hy = __float2bfloat16(y);
            __nv_bfloat16 hz = __float2bfloat16(z), hw = __float2bfloat16(w);
            uint32_t so0 = sw128(off), so1 = sw128(off + 4);
            *(uint32_t*)(smem + E1_AH + so0) = packbf(__bfloat162float(hx), __bfloat162float(hy));
            *(uint32_t*)(smem + E1_AH + so1) = packbf(__bfloat162float(hz), __bfloat162float(hw));
            *(uint32_t*)(smem + E1_AL + so0) =
                packbf(x - __bfloat162float(hx), y - __bfloat162float(hy));
            *(uint32_t*)(smem + E1_AL + so1) =
                packbf(z - __bfloat162float(hz), w - __bfloat162float(hw));
        }
        // B: straight copy into SW128 smem (128B rows, [n][k])
        #pragma unroll
        for (int u = 0; u < 4; ++u) {
            int f = tid + u * 256;
            int n = f >> 3, kq = f & 7;
            uint32_t so = sw128((uint32_t)(n * 128 + kq * 16));
            *(float4*)(smem + E1_BH + so) = bh[u];
            *(float4*)(smem + E1_BL + so) = bl[u];
        }
        __syncthreads();

        // 4 k16-steps of MMA
        #pragma unroll
        for (int ks = 0; ks < 4; ++ks) {
            uint32_t ah[2][4], al[2][4];
            #pragma unroll
            for (int ma = 0; ma < 2; ++ma) {
                uint32_t off = (uint32_t)((a_r + ma * 16) * 128 + ks * 32 + a_kb);
                LDSM4(ah[ma], sb + E1_AH + sw128(off));
                LDSM4(al[ma], sb + E1_AL + sw128(off));
            }
            uint32_t bhf[4][4], blf[4][4];
            #pragma unroll
            for (int np = 0; np < 4; ++np) {
                uint32_t off = (uint32_t)((b_n + np * 16) * 128 + ks * 32 + b_kb);
                LDSM4(bhf[np], sb + E1_BH + sw128(off));
                LDSM4(blf[np], sb + E1_BL + sw128(off));
            }
            #pragma unroll
            for (int ma = 0; ma < 2; ++ma)
                #pragma unroll
                for (int np = 0; np < 4; ++np)
                    #pragma unroll
                    for (int hf = 0; hf < 2; ++hf) {
                        const int na = np * 2 + hf;
                        MMA_BF16(acc[ma][na], ah[ma], bhf[np][hf*2], bhf[np][hf*2+1]);
                        MMA_BF16(acc[ma][na], ah[ma], blf[np][hf*2], blf[np][hf*2+1]);
                        MMA_BF16(acc[ma][na], al[ma], bhf[np][hf*2], bhf[np][hf*2+1]);
                    }
        }
    }

    // epilogue: bias + leaky, write to g_H1
    const int er = lane >> 2;
    const int ec = (lane & 3) * 2;
    #pragma unroll
    for (int ma = 0; ma < 2; ++ma) {
        #pragma unroll
        for (int na = 0; na < 8; ++na) {
            int row = bm + wm + ma * 16 + er;
            int col = bn + wn + na * 8 + ec;
            float b0 = __ldg(bias1 + col), b1 = __ldg(bias1 + col + 1);
            float f0 = acc[ma][na][0] + b0;
            float f1 = acc[ma][na][1] + b1;
            float f2 = acc[ma][na][2] + b0;
            float f3 = acc[ma][na][3] + b1;
            f0 = f0 >= 0.f ? f0 : 0.01f * f0;
            f1 = f1 >= 0.f ? f1 : 0.01f * f1;
            f2 = f2 >= 0.f ? f2 : 0.01f * f2;
            f3 = f3 >= 0.f ? f3 : 0.01f * f3;
            *(float2*)(g_H1 + (size_t)row * H1DIM + col)       = make_float2(f0, f1);
            *(float2*)(g_H1 + (size_t)(row + 8) * H1DIM + col) = make_float2(f2, f3);
        }
    }
}

// ---------------------------------------------------------------------------
// K2: Xe = H1 @ W2 + b2   M=65536 K=256 N=64 ; 128x64x16, 8x4/thread
// ---------------------------------------------------------------------------
__global__ __launch_bounds__(256)
void k_enc2(const float* __restrict__ W2, const float* __restrict__ bias2)
{
    __shared__ float As[2][16][132];
    __shared__ float Bs[2][16][64];
    const int bm = blockIdx.x * 128;
    const int tid = threadIdx.x;

    const int ar0 = tid >> 2;
    const int ar1 = ar0 + 64;
    const int ak  = (tid & 3) * 4;
    const int bk  = tid >> 4;
    const int bn4 = (tid & 15) * 4;

    const float* Ag = g_H1 + (size_t)bm * H1DIM;

    float4 a0, a1, b0;
    a0 = *(const float4*)(Ag + (size_t)ar0 * H1DIM + ak);
    a1 = *(const float4*)(Ag + (size_t)ar1 * H1DIM + ak);
    b0 = *(const float4*)(W2 + (size_t)bk * EDIM + bn4);
    As[0][ak+0][ar0] = a0.x; As[0][ak+1][ar0] = a0.y; As[0][ak+2][ar0] = a0.z; As[0][ak+3][ar0] = a0.w;
    As[0][ak+0][ar1] = a1.x; As[0][ak+1][ar1] = a1.y; As[0][ak+2][ar1] = a1.z; As[0][ak+3][ar1] = a1.w;
    *(float4*)&Bs[0][bk][bn4] = b0;
    __syncthreads();

    const int tx = tid & 15, ty = tid >> 4;
    const int tm = ty * 8, tn = tx * 4;
    float acc[8][4] = {};

    #pragma unroll 1
    for (int kt = 0; kt < 16; ++kt) {
        const int cur = kt & 1;
        if (kt < 15) {
            const float* Ap = Ag + (kt + 1) * 16;
            a0 = *(const float4*)(Ap + (size_t)ar0 * H1DIM + ak);
            a1 = *(const float4*)(Ap + (size_t)ar1 * H1DIM + ak);
            b0 = *(const float4*)(W2 + (size_t)((kt + 1) * 16 + bk) * EDIM + bn4);
        }
        #pragma unroll
        for (int kk = 0; kk < 16; ++kk) {
            float4 av0 = *(float4*)&As[cur][kk][tm];
            float4 av1 = *(float4*)&As[cur][kk][tm + 4];
            float4 bv  = *(float4*)&Bs[cur][kk][tn];
            float aa[8] = {av0.x, av0.y, av0.z, av0.w, av1.x, av1.y, av1.z, av1.w};
            float bb[4] = {bv.x, bv.y, bv.z, bv.w};
            #pragma unroll
            for (int ii = 0; ii < 8; ++ii)
                #pragma unroll
                for (int jj = 0; jj < 4; ++jj)
                    acc[ii][jj] = fmaf(aa[ii], bb[jj], acc[ii][jj]);
        }
        if (kt < 15) {
            const int nx = cur ^ 1;
            As[nx][ak+0][ar0] = a0.x; As[nx][ak+1][ar0] = a0.y; As[nx][ak+2][ar0] = a0.z; As[nx][ak+3][ar0] = a0.w;
            As[nx][ak+0][ar1] = a1.x; As[nx][ak+1][ar1] = a1.y; As[nx][ak+2][ar1] = a1.z; As[nx][ak+3][ar1] = a1.w;
            *(float4*)&Bs[nx][bk][bn4] = b0;
            __syncthreads();
        }
    }

    float bv2[4];
    #pragma unroll
    for (int j = 0; j < 4; ++j) bv2[j] = bias2[tn + j];
    #pragma unroll
    for (int ii = 0; ii < 8; ++ii) {
        float4 o = make_float4(acc[ii][0] + bv2[0], acc[ii][1] + bv2[1],
                               acc[ii][2] + bv2[2], acc[ii][3] + bv2[3]);
        *(float4*)(g_Xe + (size_t)(bm + tm + ii) * EDIM + tn) = o;
    }
}

// ---------------------------------------------------------------------------
// K3: per-patch mean
// ---------------------------------------------------------------------------
__global__ void k_patch()
{
    const int c = threadIdx.x;
    const int h = blockIdx.x;
    const int b = blockIdx.y;
    const float* base = g_Xe + ((size_t)b * 4096 + (size_t)h * 8) * EDIM + c;
    float s = 0.0f;
    #pragma unroll
    for (int p = 0; p < 16; ++p) s += base[(size_t)p * EDIM];
    g_P[((size_t)b * NPAT + h) * EDIM + c] = s * 0.0625f;
}

// ---------------------------------------------------------------------------
// relu(tanh(m)) via odd deg-11 Taylor (|m|<=0.5), MUFU-free
// ---------------------------------------------------------------------------
__device__ __forceinline__ float arelu(float xi, float yi, float xj, float yj)
{
    float m  = fmaf(xi, yj, -(yi * xj));
    float m2 = m * m;
    float t;
    if (m2 > 0.25f) {
        t = tanhf(m);
    } else {
        float p = fmaf(m2, -8.863236e-3f, 2.1869488e-2f);
        p = fmaf(m2, p, -5.3968254e-2f);
        p = fmaf(m2, p,  1.3333334e-1f);
        p = fmaf(m2, p, -3.3333334e-1f);
        t = fmaf(m * m2, p, m);
    }
    return fmaxf(t, 0.0f);
}

// ---------------------------------------------------------------------------
// K4: attention + aggregation (74.8us measured)
// ---------------------------------------------------------------------------
__global__ __launch_bounds__(512)
void k_attn(const float* __restrict__ Wq, const float* __restrict__ Wk,
            const float* __restrict__ Wv, const float* __restrict__ Wa,
            const float* __restrict__ ba)
{
    __shared__ float sWq[4096];
    __shared__ float sWk[4096];
    __shared__ float sp[512];
    __shared__ float sqn[512];
    __shared__ float skn[512];
    __shared__ float sv[512];
    __shared__ float sav[512];
    __shared__ float sred[32];

    const int tid = threadIdx.x;
    #pragma unroll
    for (int idx = tid; idx < 4096; idx += 512) {
        sWq[idx] = Wq[idx];
        sWk[idx] = Wk[idx];
    }
    const int r = tid >> 6;
    const int i = tid & 63;
    const int n = blockIdx.x * 8 + r;
    sp[tid] = g_P[(size_t)n * EDIM + i];
    __syncthreads();

    float q = 0.f, k = 0.f, v = 0.f;
    const float* prow = sp + r * 64;
    #pragma unroll 8
    for (int j = 0; j < 64; ++j) {
        float pj = prow[j];
        q = fmaf(pj, sWq[j * 64 + i], q);
        k = fmaf(pj, sWk[j * 64 + i], k);
        v = fmaf(pj, __ldg(Wv + j * 64 + i), v);
    }
    float q2 = q * q, k2 = k * k;
    #pragma unroll
    for (int o = 16; o > 0; o >>= 1) {
        q2 += __shfl_xor_sync(0xffffffffu, q2, o);
        k2 += __shfl_xor_sync(0xffffffffu, k2, o);
    }
    if ((i & 31) == 0) {
        int w = i >> 5;
        sred[r * 4 + w]     = q2;
        sred[r * 4 + 2 + w] = k2;
    }
    __syncthreads();
    const float invq = 1.0f / (sqrtf(sred[r * 4 + 0] + sred[r * 4 + 1]) + 1e-8f);
    const float invk = 1.0f / (sqrtf(sred[r * 4 + 2] + sred[r * 4 + 3]) + 1e-8f);
    sqn[tid] = q * invq;
    skn[tid] = k * invk;
    sv[tid]  = v;
    __syncthreads();

    const float xi = sqn[tid];
    const float yi = skn[tid];
    const float* xr = sqn + r * 64;
    const float* yr = skn + r * 64;
    const float* vr = sv  + r * 64;

    float t0=-1e30f,t1=-1e30f,t2=-1e30f,t3=-1e30f,
          t4=-1e30f,t5=-1e30f,t6=-1e30f,t7=-1e30f;
    #pragma unroll 8
    for (int j = 0; j < 64; ++j) {
        float y = arelu(xi, yi, xr[j], yr[j]);
        float u;
        u = fminf(y, t0); t0 = fmaxf(y, t0); y = u;
        u = fminf(y, t1); t1 = fmaxf(y, t1); y = u;
        u = fminf(y, t2); t2 = fmaxf(y, t2); y = u;
        u = fminf(y, t3); t3 = fmaxf(y, t3); y = u;
        u = fminf(y, t4); t4 = fmaxf(y, t4); y = u;
        u = fminf(y, t5); t5 = fmaxf(y, t5); y = u;
        u = fminf(y, t6); t6 = fmaxf(y, t6); y = u;
        t7 = fmaxf(y, t7);
    }
    const float thr = t7;

    float S = 0.f, av = 0.f;
    #pragma unroll 8
    for (int j = 0; j < 64; ++j) {
        float a = arelu(xi, yi, xr[j], yr[j]);
        if (a > 0.0f && a >= thr) {
            S  += a;
            av  = fmaf(a, vr[j], av);
        }
    }
    av = av / fmaxf(S, 1e-8f);
    sav[tid] = av;
    __syncthreads();

    float z = ba[i];
    const float* arow = sav + r * 64;
    #pragma unroll 8
    for (int j = 0; j < 64; ++j)
        z = fmaf(arow[j], __ldg(Wa + j * 64 + i), z);
    z = z >= 0.0f ? z : 0.01f * z;
    g_Z[(size_t)n * EDIM + i] = z;
}

// ---------------------------------------------------------------------------
// K5: fused scatter-average + decoder GEMM
// ---------------------------------------------------------------------------
__global__ __launch_bounds__(256)
void k_dec(const float* __restrict__ Wd, const float* __restrict__ bd,
           float* __restrict__ out)
{
    __shared__ float Azt[64][68];
    __shared__ float Bz[64][64];
    const int bm = blockIdx.x * 64;
    const int bn = blockIdx.y * 64;
    const int tid = threadIdx.x;

    {
        int k0 = tid >> 2;
        int c0 = (tid & 3) * 16;
        const float* src = Wd + (size_t)k0 * 512 + bn + c0;
        #pragma unroll
        for (int u = 0; u < 16; u += 4)
            *(float4*)&Bz[k0][c0 + u] = *(const float4*)(src + u);
    }
    {
        int rr = tid >> 2;
        int gr = bm + rr;
        int b  = gr >> 12;
        int l  = gr & 4095;
        int hb = l >> 3;
        int h0 = hb - 1;
        float s0 = (h0 >= 0)   ? 1.0f : 0.0f;
        float s1 = (hb <= 510) ? 1.0f : 0.0f;
        float inv = 1.0f / (s0 + s1);
        const float* z0 = g_Z + ((size_t)b * NPAT + (h0 >= 0   ? h0 : 0)) * 64;
        const float* z1 = g_Z + ((size_t)b * NPAT + (hb <= 510 ? hb : 0)) * 64;
        int kq = (tid & 3) * 16;
        #pragma unroll
        for (int u = 0; u < 16; u += 4) {
            float4 a0 = *(const float4*)(z0 + kq + u);
            float4 a1 = *(const float4*)(z1 + kq + u);
            Azt[kq + u + 0][rr] = fmaf(a0.x, s0, a1.x * s1) * inv;
            Azt[kq + u + 1][rr] = fmaf(a0.y, s0, a1.y * s1) * inv;
            Azt[kq + u + 2][rr] = fmaf(a0.z, s0, a1.z * s1) * inv;
            Azt[kq + u + 3][rr] = fmaf(a0.w, s0, a1.w * s1) * inv;
        }
    }
    __syncthreads();

    const int tx = tid & 15, ty = tid >> 4;
    const int tm = ty * 4, tn = tx * 4;
    float acc[4][4] = {};
    #pragma unroll
    for (int kk = 0; kk < 64; ++kk) {
        float4 a  = *(float4*)&Azt[kk][tm];
        float4 bq = *(float4*)&Bz[kk][tn];
        float aa[4] = {a.x, a.y, a.z, a.w};
        float bb[4] = {bq.x, bq.y, bq.z, bq.w};
        #pragma unroll
        for (int ii = 0; ii < 4; ++ii)
            #pragma unroll
            for (int jj = 0; jj < 4; ++jj)
                acc[ii][jj] = fmaf(aa[ii], bb[jj], acc[ii][jj]);
    }

    float4 bias = *(const float4*)(bd + bn + tn);
    float bb[4] = {bias.x, bias.y, bias.z, bias.w};
    #pragma unroll
    for (int ii = 0; ii < 4; ++ii) {
        float* orow = out + (size_t)(bm + tm + ii) * 512 + bn + tn;
        *(float4*)orow = make_float4(acc[ii][0] + bb[0], acc[ii][1] + bb[1],
                                     acc[ii][2] + bb[2], acc[ii][3] + bb[3]);
    }
}

// ---------------------------------------------------------------------------
extern "C" void kernel_launch(void* const* d_in, const int* in_sizes, int n_in,
                              void* d_out, int out_size)
{
    const float* X  = (const float*)d_in[0];
    const float* W1 = (const float*)d_in[1];
    const float* b1 = (const float*)d_in[2];
    const float* W2 = (const float*)d_in[3];
    const float* b2 = (const float*)d_in[4];
    const float* Wq = (const float*)d_in[5];
    const float* Wk = (const float*)d_in[6];
    const float* Wv = (const float*)d_in[7];
    const float* Wa = (const float*)d_in[8];
    const float* ba = (const float*)d_in[9];
    const float* Wd = (const float*)d_in[10];
    const float* bd = (const float*)d_in[11];
    float* out = (float*)d_out;

    cudaFuncSetAttribute(k_enc1_mma,
                         cudaFuncAttributeMaxDynamicSharedMemorySize, E1_SMEM);

    k_prepW1<<<512, 256>>>(W1);
    k_enc1_mma<<<dim3(512, 2), 256, E1_SMEM>>>(X, b1);
    k_enc2<<<512, 256>>>(W2, b2);
    k_patch<<<dim3(511, 16), 64>>>();
    k_attn<<<1022, 512>>>(Wq, Wk, Wv, Wa, ba);
    k_dec<<<dim3(1024, 8), 256>>>(Wd, bd, out);
}

// round 12
// speedup vs baseline: 1.1791x; 1.1791x over previous
#include <cuda_runtime.h>
#include <cstdint>

// ---------------------------------------------------------------------------
// Shapes:  X:(16,4096,512)  W1:(512,256) b1:(256)  W2:(256,64) b2:(64)
//          Wq/Wk/Wv/Wa:(64,64) ba:(64)  Wd:(64,512) bd:(512)
// PATCH=16 STRIDE=8 TOPK=8 EPS=1e-8 ; h=511 ; N=B*h=8176 ; M=B*L=65536
// ---------------------------------------------------------------------------
#define MROWS 65536
#define DDIM  512
#define H1DIM 256
#define EDIM  64
#define NPAT  511
#define NROWS 8176

__device__ float g_H1[(size_t)MROWS * H1DIM];   // 64 MB
__device__ float g_Xe[(size_t)MROWS * EDIM];    // 16 MB
__device__ float g_P [(size_t)NROWS * EDIM];    //  2 MB
__device__ float g_Z [(size_t)NROWS * EDIM];    //  2 MB

// ---------------------------------------------------------------------------
// K1: H1 = leaky(X @ W1 + b1)   M=65536 K=512 N=256 ; 128x128x16, 8x8/thread
// grid (2, 512): bn on x so the two blocks sharing an A-tile are adjacent
// in launch order -> X tile hits L2 on the second block.
// ---------------------------------------------------------------------------
__global__ __launch_bounds__(256)
void k_enc1(const float* __restrict__ X, const float* __restrict__ W1,
            const float* __restrict__ bias1)
{
    __shared__ float As[2][16][132];
    __shared__ float Bs[2][16][128];
    const int bm = blockIdx.y * 128;
    const int bn = blockIdx.x * 128;
    const int tid = threadIdx.x;

    const int ar0 = tid >> 2;            // 0..63
    const int ar1 = ar0 + 64;
    const int ak  = (tid & 3) * 4;
    const int bk0 = tid >> 5;            // 0..7
    const int bk1 = bk0 + 8;
    const int bn4 = (tid & 31) * 4;

    const float* Ag = X + (size_t)bm * DDIM;

    float4 a0, a1, b0, b1;
    a0 = *(const float4*)(Ag + (size_t)ar0 * DDIM + ak);
    a1 = *(const float4*)(Ag + (size_t)ar1 * DDIM + ak);
    b0 = *(const float4*)(W1 + (size_t)bk0 * H1DIM + bn + bn4);
    b1 = *(const float4*)(W1 + (size_t)bk1 * H1DIM + bn + bn4);
    As[0][ak+0][ar0] = a0.x; As[0][ak+1][ar0] = a0.y; As[0][ak+2][ar0] = a0.z; As[0][ak+3][ar0] = a0.w;
    As[0][ak+0][ar1] = a1.x; As[0][ak+1][ar1] = a1.y; As[0][ak+2][ar1] = a1.z; As[0][ak+3][ar1] = a1.w;
    *(float4*)&Bs[0][bk0][bn4] = b0;
    *(float4*)&Bs[0][bk1][bn4] = b1;
    __syncthreads();

    const int tx = tid & 15, ty = tid >> 4;
    const int tm = ty * 8, tn = tx * 8;
    float acc[8][8] = {};

    #pragma unroll 1
    for (int kt = 0; kt < 32; ++kt) {
        const int cur = kt & 1;
        if (kt < 31) {
            const float* Ap = Ag + (kt + 1) * 16;
            a0 = *(const float4*)(Ap + (size_t)ar0 * DDIM + ak);
            a1 = *(const float4*)(Ap + (size_t)ar1 * DDIM + ak);
            const float* Bp = W1 + (size_t)(kt + 1) * 16 * H1DIM;
            b0 = *(const float4*)(Bp + (size_t)bk0 * H1DIM + bn + bn4);
            b1 = *(const float4*)(Bp + (size_t)bk1 * H1DIM + bn + bn4);
        }
        #pragma unroll
        for (int kk = 0; kk < 16; ++kk) {
            float4 av0 = *(float4*)&As[cur][kk][tm];
            float4 av1 = *(float4*)&As[cur][kk][tm + 4];
            float4 bv0 = *(float4*)&Bs[cur][kk][tn];
            float4 bv1 = *(float4*)&Bs[cur][kk][tn + 4];
            float aa[8] = {av0.x, av0.y, av0.z, av0.w, av1.x, av1.y, av1.z, av1.w};
            float bb[8] = {bv0.x, bv0.y, bv0.z, bv0.w, bv1.x, bv1.y, bv1.z, bv1.w};
            #pragma unroll
            for (int ii = 0; ii < 8; ++ii)
                #pragma unroll
                for (int jj = 0; jj < 8; ++jj)
                    acc[ii][jj] = fmaf(aa[ii], bb[jj], acc[ii][jj]);
        }
        if (kt < 31) {
            const int nx = cur ^ 1;
            As[nx][ak+0][ar0] = a0.x; As[nx][ak+1][ar0] = a0.y; As[nx][ak+2][ar0] = a0.z; As[nx][ak+3][ar0] = a0.w;
            As[nx][ak+0][ar1] = a1.x; As[nx][ak+1][ar1] = a1.y; As[nx][ak+2][ar1] = a1.z; As[nx][ak+3][ar1] = a1.w;
            *(float4*)&Bs[nx][bk0][bn4] = b0;
            *(float4*)&Bs[nx][bk1][bn4] = b1;
            __syncthreads();
        }
    }

    float bv[8];
    #pragma unroll
    for (int j = 0; j < 8; ++j) bv[j] = bias1[bn + tn + j];
    #pragma unroll
    for (int ii = 0; ii < 8; ++ii) {
        float o[8];
        #pragma unroll
        for (int jj = 0; jj < 8; ++jj) {
            float hx = acc[ii][jj] + bv[jj];
            o[jj] = hx >= 0.0f ? hx : 0.01f * hx;
        }
        float* orow = g_H1 + (size_t)(bm + tm + ii) * H1DIM + bn + tn;
        *(float4*)(orow)     = make_float4(o[0], o[1], o[2], o[3]);
        *(float4*)(orow + 4) = make_float4(o[4], o[5], o[6], o[7]);
    }
}

// ---------------------------------------------------------------------------
// K2: Xe = H1 @ W2 + b2   M=65536 K=256 N=64 ; 128x64x16, 8x4/thread
// ---------------------------------------------------------------------------
__global__ __launch_bounds__(256)
void k_enc2(const float* __restrict__ W2, const float* __restrict__ bias2)
{
    __shared__ float As[2][16][132];
    __shared__ float Bs[2][16][64];
    const int bm = blockIdx.x * 128;
    const int tid = threadIdx.x;

    const int ar0 = tid >> 2;
    const int ar1 = ar0 + 64;
    const int ak  = (tid & 3) * 4;
    const int bk  = tid >> 4;
    const int bn4 = (tid & 15) * 4;

    const float* Ag = g_H1 + (size_t)bm * H1DIM;

    float4 a0, a1, b0;
    a0 = *(const float4*)(Ag + (size_t)ar0 * H1DIM + ak);
    a1 = *(const float4*)(Ag + (size_t)ar1 * H1DIM + ak);
    b0 = *(const float4*)(W2 + (size_t)bk * EDIM + bn4);
    As[0][ak+0][ar0] = a0.x; As[0][ak+1][ar0] = a0.y; As[0][ak+2][ar0] = a0.z; As[0][ak+3][ar0] = a0.w;
    As[0][ak+0][ar1] = a1.x; As[0][ak+1][ar1] = a1.y; As[0][ak+2][ar1] = a1.z; As[0][ak+3][ar1] = a1.w;
    *(float4*)&Bs[0][bk][bn4] = b0;
    __syncthreads();

    const int tx = tid & 15, ty = tid >> 4;
    const int tm = ty * 8, tn = tx * 4;
    float acc[8][4] = {};

    #pragma unroll 1
    for (int kt = 0; kt < 16; ++kt) {
        const int cur = kt & 1;
        if (kt < 15) {
            const float* Ap = Ag + (kt + 1) * 16;
            a0 = *(const float4*)(Ap + (size_t)ar0 * H1DIM + ak);
            a1 = *(const float4*)(Ap + (size_t)ar1 * H1DIM + ak);
            b0 = *(const float4*)(W2 + (size_t)((kt + 1) * 16 + bk) * EDIM + bn4);
        }
        #pragma unroll
        for (int kk = 0; kk < 16; ++kk) {
            float4 av0 = *(float4*)&As[cur][kk][tm];
            float4 av1 = *(float4*)&As[cur][kk][tm + 4];
            float4 bv  = *(float4*)&Bs[cur][kk][tn];
            float aa[8] = {av0.x, av0.y, av0.z, av0.w, av1.x, av1.y, av1.z, av1.w};
            float bb[4] = {bv.x, bv.y, bv.z, bv.w};
            #pragma unroll
            for (int ii = 0; ii < 8; ++ii)
                #pragma unroll
                for (int jj = 0; jj < 4; ++jj)
                    acc[ii][jj] = fmaf(aa[ii], bb[jj], acc[ii][jj]);
        }
        if (kt < 15) {
            const int nx = cur ^ 1;
            As[nx][ak+0][ar0] = a0.x; As[nx][ak+1][ar0] = a0.y; As[nx][ak+2][ar0] = a0.z; As[nx][ak+3][ar0] = a0.w;
            As[nx][ak+0][ar1] = a1.x; As[nx][ak+1][ar1] = a1.y; As[nx][ak+2][ar1] = a1.z; As[nx][ak+3][ar1] = a1.w;
            *(float4*)&Bs[nx][bk][bn4] = b0;
            __syncthreads();
        }
    }

    float bv2[4];
    #pragma unroll
    for (int j = 0; j < 4; ++j) bv2[j] = bias2[tn + j];
    #pragma unroll
    for (int ii = 0; ii < 8; ++ii) {
        float4 o = make_float4(acc[ii][0] + bv2[0], acc[ii][1] + bv2[1],
                               acc[ii][2] + bv2[2], acc[ii][3] + bv2[3]);
        *(float4*)(g_Xe + (size_t)(bm + tm + ii) * EDIM + tn) = o;
    }
}

// ---------------------------------------------------------------------------
// K3: per-patch mean.  One float4 per thread, 16 loads in flight (MLP=16).
// total (n,c4) pairs = 8176*16 = 130816 = 511 blocks * 256 threads exactly.
// ---------------------------------------------------------------------------
__global__ __launch_bounds__(256)
void k_patch()
{
    const int g  = blockIdx.x * 256 + threadIdx.x;
    const int n  = g >> 4;
    const int c4 = (g & 15) * 4;
    const int b  = n / NPAT;
    const int h  = n - b * NPAT;
    const float* base = g_Xe + ((size_t)b * 4096 + (size_t)h * 8) * EDIM + c4;
    float4 s = make_float4(0.f, 0.f, 0.f, 0.f);
    #pragma unroll
    for (int p = 0; p < 16; ++p) {
        float4 v = *(const float4*)(base + (size_t)p * EDIM);
        s.x += v.x; s.y += v.y; s.z += v.z; s.w += v.w;
    }
    *(float4*)(g_P + (size_t)n * EDIM + c4) =
        make_float4(s.x * 0.0625f, s.y * 0.0625f, s.z * 0.0625f, s.w * 0.0625f);
}

// ---------------------------------------------------------------------------
// relu(tanh(m)) via odd deg-11 Taylor (|m|<=0.5), MUFU-free
// ---------------------------------------------------------------------------
__device__ __forceinline__ float arelu(float xi, float yi, float xj, float yj)
{
    float m  = fmaf(xi, yj, -(yi * xj));
    float m2 = m * m;
    float t;
    if (m2 > 0.25f) {
        t = tanhf(m);
    } else {
        float p = fmaf(m2, -8.863236e-3f, 2.1869488e-2f);
        p = fmaf(m2, p, -5.3968254e-2f);
        p = fmaf(m2, p,  1.3333334e-1f);
        p = fmaf(m2, p, -3.3333334e-1f);
        t = fmaf(m * m2, p, m);
    }
    return fmaxf(t, 0.0f);
}

// ---------------------------------------------------------------------------
// K4: attention + aggregation.  SINGLE PASS: pack patch index j into the low
// 6 mantissa bits of the fp32 A-value (monotone for y>=0, perturbation
// <= 7.5e-6 relative).  The sorted top-8 chain then yields both the masked
// sum S and the kept indices (8 smem gathers for Av) -- no second pass.
// Zero-valued entries pack to denormals and contribute ~0, matching
// reference tie semantics at zero.
// ---------------------------------------------------------------------------
__global__ __launch_bounds__(512)
void k_attn(const float* __restrict__ Wq, const float* __restrict__ Wk,
            const float* __restrict__ Wv, const float* __restrict__ Wa,
            const float* __restrict__ ba)
{
    __shared__ float sWq[4096];
    __shared__ float sWk[4096];
    __shared__ float sp[512];
    __shared__ float sqn[512];
    __shared__ float skn[512];
    __shared__ float sv[512];
    __shared__ float sav[512];
    __shared__ float sred[32];

    const int tid = threadIdx.x;
    #pragma unroll
    for (int idx = tid; idx < 4096; idx += 512) {
        sWq[idx] = Wq[idx];
        sWk[idx] = Wk[idx];
    }
    const int r = tid >> 6;
    const int i = tid & 63;
    const int n = blockIdx.x * 8 + r;
    sp[tid] = g_P[(size_t)n * EDIM + i];
    __syncthreads();

    float q = 0.f, k = 0.f, v = 0.f;
    const float* prow = sp + r * 64;
    #pragma unroll 8
    for (int j = 0; j < 64; ++j) {
        float pj = prow[j];
        q = fmaf(pj, sWq[j * 64 + i], q);
        k = fmaf(pj, sWk[j * 64 + i], k);
        v = fmaf(pj, __ldg(Wv + j * 64 + i), v);
    }
    float q2 = q * q, k2 = k * k;
    #pragma unroll
    for (int o = 16; o > 0; o >>= 1) {
        q2 += __shfl_xor_sync(0xffffffffu, q2, o);
        k2 += __shfl_xor_sync(0xffffffffu, k2, o);
    }
    if ((i & 31) == 0) {
        int w = i >> 5;
        sred[r * 4 + w]     = q2;
        sred[r * 4 + 2 + w] = k2;
    }
    __syncthreads();
    const float invq = 1.0f / (sqrtf(sred[r * 4 + 0] + sred[r * 4 + 1]) + 1e-8f);
    const float invk = 1.0f / (sqrtf(sred[r * 4 + 2] + sred[r * 4 + 3]) + 1e-8f);
    sqn[tid] = q * invq;
    skn[tid] = k * invk;
    sv[tid]  = v;
    __syncthreads();

    const float xi = sqn[tid];
    const float yi = skn[tid];
    const float* xr = sqn + r * 64;
    const float* yr = skn + r * 64;
    const float* vr = sv  + r * 64;

    // single pass: streaming sorted top-8 of index-packed values
    float t0=-1e30f,t1=-1e30f,t2=-1e30f,t3=-1e30f,
          t4=-1e30f,t5=-1e30f,t6=-1e30f,t7=-1e30f;
    #pragma unroll 8
    for (int j = 0; j < 64; ++j) {
        float a = arelu(xi, yi, xr[j], yr[j]);
        float y = __uint_as_float((__float_as_uint(a) & 0xFFFFFFC0u) | (uint32_t)j);
        float u;
        u = fminf(y, t0); t0 = fmaxf(y, t0); y = u;
        u = fminf(y, t1); t1 = fmaxf(y, t1); y = u;
        u = fminf(y, t2); t2 = fmaxf(y, t2); y = u;
        u = fminf(y, t3); t3 = fmaxf(y, t3); y = u;
        u = fminf(y, t4); t4 = fmaxf(y, t4); y = u;
        u = fminf(y, t5); t5 = fmaxf(y, t5); y = u;
        u = fminf(y, t6); t6 = fmaxf(y, t6); y = u;
        t7 = fmaxf(y, t7);
    }

    float S  = ((t0 + t1) + (t2 + t3)) + ((t4 + t5) + (t6 + t7));
    float av = 0.f;
    av = fmaf(t0, vr[__float_as_uint(t0) & 63u], av);
    av = fmaf(t1, vr[__float_as_uint(t1) & 63u], av);
    av = fmaf(t2, vr[__float_as_uint(t2) & 63u], av);
    av = fmaf(t3, vr[__float_as_uint(t3) & 63u], av);
    av = fmaf(t4, vr[__float_as_uint(t4) & 63u], av);
    av = fmaf(t5, vr[__float_as_uint(t5) & 63u], av);
    av = fmaf(t6, vr[__float_as_uint(t6) & 63u], av);
    av = fmaf(t7, vr[__float_as_uint(t7) & 63u], av);
    av = av / fmaxf(S, 1e-8f);
    sav[tid] = av;
    __syncthreads();

    float z = ba[i];
    const float* arow = sav + r * 64;
    #pragma unroll 8
    for (int j = 0; j < 64; ++j)
        z = fmaf(arow[j], __ldg(Wa + j * 64 + i), z);
    z = z >= 0.0f ? z : 0.01f * z;
    g_Z[(size_t)n * EDIM + i] = z;
}

// ---------------------------------------------------------------------------
// K5: fused scatter-average + decoder GEMM
// ---------------------------------------------------------------------------
__global__ __launch_bounds__(256)
void k_dec(const float* __restrict__ Wd, const float* __restrict__ bd,
           float* __restrict__ out)
{
    __shared__ float Azt[64][68];
    __shared__ float Bz[64][64];
    const int bm = blockIdx.x * 64;
    const int bn = blockIdx.y * 64;
    const int tid = threadIdx.x;

    {
        int k0 = tid >> 2;
        int c0 = (tid & 3) * 16;
        const float* src = Wd + (size_t)k0 * 512 + bn + c0;
        #pragma unroll
        for (int u = 0; u < 16; u += 4)
            *(float4*)&Bz[k0][c0 + u] = *(const float4*)(src + u);
    }
    {
        int rr = tid >> 2;
        int gr = bm + rr;
        int b  = gr >> 12;
        int l  = gr & 4095;
        int hb = l >> 3;
        int h0 = hb - 1;
        float s0 = (h0 >= 0)   ? 1.0f : 0.0f;
        float s1 = (hb <= 510) ? 1.0f : 0.0f;
        float inv = 1.0f / (s0 + s1);
        const float* z0 = g_Z + ((size_t)b * NPAT + (h0 >= 0   ? h0 : 0)) * 64;
        const float* z1 = g_Z + ((size_t)b * NPAT + (hb <= 510 ? hb : 0)) * 64;
        int kq = (tid & 3) * 16;
        #pragma unroll
        for (int u = 0; u < 16; u += 4) {
            float4 a0 = *(const float4*)(z0 + kq + u);
            float4 a1 = *(const float4*)(z1 + kq + u);
            Azt[kq + u + 0][rr] = fmaf(a0.x, s0, a1.x * s1) * inv;
            Azt[kq + u + 1][rr] = fmaf(a0.y, s0, a1.y * s1) * inv;
            Azt[kq + u + 2][rr] = fmaf(a0.z, s0, a1.z * s1) * inv;
            Azt[kq + u + 3][rr] = fmaf(a0.w, s0, a1.w * s1) * inv;
        }
    }
    __syncthreads();

    const int tx = tid & 15, ty = tid >> 4;
    const int tm = ty * 4, tn = tx * 4;
    float acc[4][4] = {};
    #pragma unroll
    for (int kk = 0; kk < 64; ++kk) {
        float4 a  = *(float4*)&Azt[kk][tm];
        float4 bq = *(float4*)&Bz[kk][tn];
        float aa[4] = {a.x, a.y, a.z, a.w};
        float bb[4] = {bq.x, bq.y, bq.z, bq.w};
        #pragma unroll
        for (int ii = 0; ii < 4; ++ii)
            #pragma unroll
            for (int jj = 0; jj < 4; ++jj)
                acc[ii][jj] = fmaf(aa[ii], bb[jj], acc[ii][jj]);
    }

    float4 bias = *(const float4*)(bd + bn + tn);
    float bb[4] = {bias.x, bias.y, bias.z, bias.w};
    #pragma unroll
    for (int ii = 0; ii < 4; ++ii) {
        float* orow = out + (size_t)(bm + tm + ii) * 512 + bn + tn;
        *(float4*)orow = make_float4(acc[ii][0] + bb[0], acc[ii][1] + bb[1],
                                     acc[ii][2] + bb[2], acc[ii][3] + bb[3]);
    }
}

// ---------------------------------------------------------------------------
extern "C" void kernel_launch(void* const* d_in, const int* in_sizes, int n_in,
                              void* d_out, int out_size)
{
    const float* X  = (const float*)d_in[0];
    const float* W1 = (const float*)d_in[1];
    const float* b1 = (const float*)d_in[2];
    const float* W2 = (const float*)d_in[3];
    const float* b2 = (const float*)d_in[4];
    const float* Wq = (const float*)d_in[5];
    const float* Wk = (const float*)d_in[6];
    const float* Wv = (const float*)d_in[7];
    const float* Wa = (const float*)d_in[8];
    const float* ba = (const float*)d_in[9];
    const float* Wd = (const float*)d_in[10];
    const float* bd = (const float*)d_in[11];
    float* out = (float*)d_out;

    k_enc1<<<dim3(2, 512), 256>>>(X, W1, b1);
    k_enc2<<<512, 256>>>(W2, b2);
    k_patch<<<511, 256>>>();
    k_attn<<<1022, 512>>>(Wq, Wk, Wv, Wa, ba);
    k_dec<<<dim3(1024, 8), 256>>>(Wd, bd, out);
}